// round 3
// baseline (speedup 1.0000x reference)
#include <cuda_runtime.h>

// Problem constants
#define BB    128
#define SS    196
#define DIN   512
#define HH    8
#define DKK   32
#define DVV   128
#define QKVD  1536
#define PROJD 1024
#define MROWS 25088          // B*S
#define SCALE_ATT 0.17677669529663689f   // 32^-0.5

// Scratch (device globals: allocation-free rule)
__device__ float g_q[128*8*196*32];       // [B,H,S,DK]
__device__ float g_k[128*8*196*32];       // [B,H,S,DK]
__device__ float g_v[128*8*196*128];      // [B,H,S,DV]
__device__ float g_hidden[25088*1024];    // [B,S',1024] (scrambled layout, post hard-swish)
__device__ float g_s1[1536], g_t1[1536];
__device__ float g_s2[512],  g_t2[512];

// ---------------------------------------------------------------------------
// Fold BN (+bias) into scale/shift:  y = (xW + b) bn->  xW * s + t
// ---------------------------------------------------------------------------
__global__ void prep_kernel(const float* __restrict__ b_qkv,
                            const float* __restrict__ gamma1, const float* __restrict__ beta1,
                            const float* __restrict__ mean1,  const float* __restrict__ var1,
                            const float* __restrict__ b_proj,
                            const float* __restrict__ gamma2, const float* __restrict__ beta2,
                            const float* __restrict__ mean2,  const float* __restrict__ var2) {
    int i = blockIdx.x * blockDim.x + threadIdx.x;
    if (i < 1536) {
        float s = gamma1[i] * rsqrtf(var1[i] + 1e-3f);
        g_s1[i] = s;
        g_t1[i] = (b_qkv[i] - mean1[i]) * s + beta1[i];
    }
    if (i < 512) {
        float s = gamma2[i] * rsqrtf(var2[i] + 1e-3f);
        g_s2[i] = s;
        g_t2[i] = (b_proj[i] - mean2[i]) * s + beta2[i];
    }
}

// ---------------------------------------------------------------------------
// GEMM1: C[25088,1536] = x[25088,512] @ W_qkv[512,1536]; BN-fold; scatter q/k/v
// 64x64 tile, BK=16, 256 threads, 4x4 micro-tile
// ---------------------------------------------------------------------------
__global__ __launch_bounds__(256) void gemm1_kernel(const float* __restrict__ x,
                                                    const float* __restrict__ W) {
    __shared__ float As[16][68];   // [k][m], padded for alignment
    __shared__ float Bs[16][64];   // [k][n]
    int tid = threadIdx.x;
    int m0 = blockIdx.y * 64;
    int n0 = blockIdx.x * 64;
    int tn = tid & 15;             // lane-fast over n -> coalesced epilogue
    int tm = tid >> 4;
    int arow = tid >> 2, acol = (tid & 3) << 2;
    int brow = tid >> 4, bcol = (tid & 15) << 2;

    float acc[4][4];
    #pragma unroll
    for (int i = 0; i < 4; i++)
        #pragma unroll
        for (int j = 0; j < 4; j++) acc[i][j] = 0.f;

    for (int k0 = 0; k0 < 512; k0 += 16) {
        float4 av = *(const float4*)&x[(size_t)(m0 + arow) * 512 + k0 + acol];
        float4 bv = *(const float4*)&W[(size_t)(k0 + brow) * 1536 + n0 + bcol];
        As[acol + 0][arow] = av.x;
        As[acol + 1][arow] = av.y;
        As[acol + 2][arow] = av.z;
        As[acol + 3][arow] = av.w;
        *(float4*)&Bs[brow][bcol] = bv;
        __syncthreads();
        #pragma unroll
        for (int k = 0; k < 16; k++) {
            float4 a = *(float4*)&As[k][tm << 2];
            float4 b = *(float4*)&Bs[k][tn << 2];
            acc[0][0] = fmaf(a.x, b.x, acc[0][0]);
            acc[0][1] = fmaf(a.x, b.y, acc[0][1]);
            acc[0][2] = fmaf(a.x, b.z, acc[0][2]);
            acc[0][3] = fmaf(a.x, b.w, acc[0][3]);
            acc[1][0] = fmaf(a.y, b.x, acc[1][0]);
            acc[1][1] = fmaf(a.y, b.y, acc[1][1]);
            acc[1][2] = fmaf(a.y, b.z, acc[1][2]);
            acc[1][3] = fmaf(a.y, b.w, acc[1][3]);
            acc[2][0] = fmaf(a.z, b.x, acc[2][0]);
            acc[2][1] = fmaf(a.z, b.y, acc[2][1]);
            acc[2][2] = fmaf(a.z, b.z, acc[2][2]);
            acc[2][3] = fmaf(a.z, b.w, acc[2][3]);
            acc[3][0] = fmaf(a.w, b.x, acc[3][0]);
            acc[3][1] = fmaf(a.w, b.y, acc[3][1]);
            acc[3][2] = fmaf(a.w, b.z, acc[3][2]);
            acc[3][3] = fmaf(a.w, b.w, acc[3][3]);
        }
        __syncthreads();
    }

    // Epilogue: BN fold + scatter to q/k/v layouts [B,H,S,*]
    #pragma unroll
    for (int i = 0; i < 4; i++) {
        int m = m0 + (tm << 2) + i;
        int bb = m / 196;
        int s  = m - bb * 196;
        #pragma unroll
        for (int jj = 0; jj < 4; jj++) {
            int j = n0 + (tn << 2) + jj;
            float v = fmaf(acc[i][jj], g_s1[j], g_t1[j]);
            int h = j / 192;
            int r = j - h * 192;
            size_t bhs = (size_t)(bb * 8 + h) * 196 + s;
            if (r < 32)       g_q[bhs * 32 + r] = v;
            else if (r < 64)  g_k[bhs * 32 + (r - 32)] = v;
            else              g_v[bhs * 128 + (r - 64)] = v;
        }
    }
}

// ---------------------------------------------------------------------------
// Attention: one CTA per (b,h). K,V resident in smem; query tiles of 64.
// Scores -> softmax -> AV -> hard_swish -> scrambled store to g_hidden
// ---------------------------------------------------------------------------
#define KSP 33
#define PSP 66
#define QSP 68
#define ATTN_SMEM_FLOATS (196*KSP + 196*128 + 196*PSP + 32*QSP)
#define ATTN_SMEM_BYTES  (ATTN_SMEM_FLOATS * 4)

__global__ __launch_bounds__(256) void attn_kernel() {
    extern __shared__ float sm[];
    float* Ks = sm;                       // [196][33]
    float* Vs = Ks + 196 * KSP;           // [196][128]
    float* Ps = Vs + 196 * 128;           // [j=196][s=66 pad] transposed probs
    float* Qs = Ps + 196 * PSP;           // [d=32][s=68 pad]

    int bh = blockIdx.x;
    int bb = bh >> 3, h = bh & 7;
    const float* qg = g_q + (size_t)bh * 196 * 32;
    const float* kg = g_k + (size_t)bh * 196 * 32;
    const float* vg = g_v + (size_t)bh * 196 * 128;
    int tid = threadIdx.x, w = tid >> 5, l = tid & 31;

    for (int i = tid; i < 196 * 32; i += 256)
        Ks[(i >> 5) * KSP + (i & 31)] = kg[i];
    for (int i = tid; i < 196 * 128; i += 256)
        Vs[i] = vg[i];
    __syncthreads();

    for (int t0 = 0; t0 < 196; t0 += 64) {
        int nr = min(64, 196 - t0);
        // stage Q tile transposed: Qs[d][s]
        for (int i = tid; i < nr * 32; i += 256) {
            int s = i >> 5, d = i & 31;
            Qs[d * QSP + s] = qg[(t0 + s) * 32 + d];
        }
        __syncthreads();

        // ---- score GEMM: warp w -> rows [8w,8w+8), lane l -> keys j=l+32t
        float acc[56];
        #pragma unroll
        for (int i = 0; i < 56; i++) acc[i] = 0.f;
        int s0 = w << 3;
        #pragma unroll 4
        for (int d = 0; d < 32; d++) {
            float4 qa = *(float4*)(Qs + d * QSP + s0);
            float4 qb = *(float4*)(Qs + d * QSP + s0 + 4);
            #pragma unroll
            for (int t = 0; t < 7; t++) {
                int j = l + (t << 5);
                float kv = Ks[(j < 196 ? j : 195) * KSP + d];
                acc[t * 8 + 0] = fmaf(qa.x, kv, acc[t * 8 + 0]);
                acc[t * 8 + 1] = fmaf(qa.y, kv, acc[t * 8 + 1]);
                acc[t * 8 + 2] = fmaf(qa.z, kv, acc[t * 8 + 2]);
                acc[t * 8 + 3] = fmaf(qa.w, kv, acc[t * 8 + 3]);
                acc[t * 8 + 4] = fmaf(qb.x, kv, acc[t * 8 + 4]);
                acc[t * 8 + 5] = fmaf(qb.y, kv, acc[t * 8 + 5]);
                acc[t * 8 + 6] = fmaf(qb.z, kv, acc[t * 8 + 6]);
                acc[t * 8 + 7] = fmaf(qb.w, kv, acc[t * 8 + 7]);
            }
        }
        // scatter scores (transposed) into Ps[j][s]
        #pragma unroll
        for (int t = 0; t < 7; t++) {
            int j = l + (t << 5);
            if (j < 196) {
                #pragma unroll
                for (int i = 0; i < 8; i++)
                    Ps[j * PSP + s0 + i] = acc[t * 8 + i];
            }
        }
        __syncthreads();

        // ---- softmax over keys for each row (warp-parallel)
        for (int r = w; r < nr; r += 8) {
            float v[7];
            #pragma unroll
            for (int t = 0; t < 7; t++) {
                int j = l + (t << 5);
                v[t] = (j < 196) ? Ps[j * PSP + r] * SCALE_ATT : -1e30f;
            }
            float mx = v[0];
            #pragma unroll
            for (int t = 1; t < 7; t++) mx = fmaxf(mx, v[t]);
            #pragma unroll
            for (int o = 16; o > 0; o >>= 1)
                mx = fmaxf(mx, __shfl_xor_sync(0xffffffffu, mx, o));
            float sum = 0.f;
            #pragma unroll
            for (int t = 0; t < 7; t++) {
                int j = l + (t << 5);
                v[t] = (j < 196) ? __expf(v[t] - mx) : 0.f;
                sum += v[t];
            }
            #pragma unroll
            for (int o = 16; o > 0; o >>= 1)
                sum += __shfl_xor_sync(0xffffffffu, sum, o);
            float inv = 1.0f / sum;
            #pragma unroll
            for (int t = 0; t < 7; t++) {
                int j = l + (t << 5);
                if (j < 196) Ps[j * PSP + r] = v[t] * inv;
            }
        }
        __syncthreads();

        // ---- AV GEMM: lane l -> rows {l, l+32}; warp w -> d in [16w,16w+16)
        float acc2[32];
        #pragma unroll
        for (int i = 0; i < 32; i++) acc2[i] = 0.f;
        int d0 = w << 4;
        for (int j = 0; j < 196; j++) {
            float p0 = Ps[j * PSP + l];
            float p1 = Ps[j * PSP + l + 32];
            const float* vrow = Vs + j * 128 + d0;
            float4 v0 = *(float4*)(vrow);
            float4 v1 = *(float4*)(vrow + 4);
            float4 v2 = *(float4*)(vrow + 8);
            float4 v3 = *(float4*)(vrow + 12);
            acc2[ 0] = fmaf(p0, v0.x, acc2[ 0]);
            acc2[ 1] = fmaf(p0, v0.y, acc2[ 1]);
            acc2[ 2] = fmaf(p0, v0.z, acc2[ 2]);
            acc2[ 3] = fmaf(p0, v0.w, acc2[ 3]);
            acc2[ 4] = fmaf(p0, v1.x, acc2[ 4]);
            acc2[ 5] = fmaf(p0, v1.y, acc2[ 5]);
            acc2[ 6] = fmaf(p0, v1.z, acc2[ 6]);
            acc2[ 7] = fmaf(p0, v1.w, acc2[ 7]);
            acc2[ 8] = fmaf(p0, v2.x, acc2[ 8]);
            acc2[ 9] = fmaf(p0, v2.y, acc2[ 9]);
            acc2[10] = fmaf(p0, v2.z, acc2[10]);
            acc2[11] = fmaf(p0, v2.w, acc2[11]);
            acc2[12] = fmaf(p0, v3.x, acc2[12]);
            acc2[13] = fmaf(p0, v3.y, acc2[13]);
            acc2[14] = fmaf(p0, v3.z, acc2[14]);
            acc2[15] = fmaf(p0, v3.w, acc2[15]);
            acc2[16] = fmaf(p1, v0.x, acc2[16]);
            acc2[17] = fmaf(p1, v0.y, acc2[17]);
            acc2[18] = fmaf(p1, v0.z, acc2[18]);
            acc2[19] = fmaf(p1, v0.w, acc2[19]);
            acc2[20] = fmaf(p1, v1.x, acc2[20]);
            acc2[21] = fmaf(p1, v1.y, acc2[21]);
            acc2[22] = fmaf(p1, v1.z, acc2[22]);
            acc2[23] = fmaf(p1, v1.w, acc2[23]);
            acc2[24] = fmaf(p1, v2.x, acc2[24]);
            acc2[25] = fmaf(p1, v2.y, acc2[25]);
            acc2[26] = fmaf(p1, v2.z, acc2[26]);
            acc2[27] = fmaf(p1, v2.w, acc2[27]);
            acc2[28] = fmaf(p1, v3.x, acc2[28]);
            acc2[29] = fmaf(p1, v3.y, acc2[29]);
            acc2[30] = fmaf(p1, v3.z, acc2[30]);
            acc2[31] = fmaf(p1, v3.w, acc2[31]);
        }

        // ---- hard_swish + faithful scramble store:
        // hidden[b, flat/1024, flat%1024] with flat = h*DV*S + d*S + s
        size_t base = (size_t)bb * 200704 + (size_t)h * 25088 + t0;
        #pragma unroll
        for (int g = 0; g < 2; g++) {
            int sl = l + (g << 5);
            if (sl < nr) {
                #pragma unroll
                for (int t = 0; t < 16; t++) {
                    float xv = acc2[g * 16 + t];
                    float hs = xv * __saturatef((xv + 3.0f) * (1.0f / 6.0f));
                    g_hidden[base + (size_t)(d0 + t) * 196 + sl] = hs;
                }
            }
        }
        __syncthreads();
    }
}

// ---------------------------------------------------------------------------
// GEMM2: out[25088,512] = hidden[25088,1024] @ W_proj[1024,512]; BN fold
// ---------------------------------------------------------------------------
__global__ __launch_bounds__(256) void gemm2_kernel(const float* __restrict__ W,
                                                    float* __restrict__ out) {
    __shared__ float As[16][68];
    __shared__ float Bs[16][64];
    int tid = threadIdx.x;
    int m0 = blockIdx.y * 64;
    int n0 = blockIdx.x * 64;
    int tn = tid & 15;
    int tm = tid >> 4;
    int arow = tid >> 2, acol = (tid & 3) << 2;
    int brow = tid >> 4, bcol = (tid & 15) << 2;

    float acc[4][4];
    #pragma unroll
    for (int i = 0; i < 4; i++)
        #pragma unroll
        for (int j = 0; j < 4; j++) acc[i][j] = 0.f;

    for (int k0 = 0; k0 < 1024; k0 += 16) {
        float4 av = *(const float4*)&g_hidden[(size_t)(m0 + arow) * 1024 + k0 + acol];
        float4 bv = *(const float4*)&W[(size_t)(k0 + brow) * 512 + n0 + bcol];
        As[acol + 0][arow] = av.x;
        As[acol + 1][arow] = av.y;
        As[acol + 2][arow] = av.z;
        As[acol + 3][arow] = av.w;
        *(float4*)&Bs[brow][bcol] = bv;
        __syncthreads();
        #pragma unroll
        for (int k = 0; k < 16; k++) {
            float4 a = *(float4*)&As[k][tm << 2];
            float4 b = *(float4*)&Bs[k][tn << 2];
            acc[0][0] = fmaf(a.x, b.x, acc[0][0]);
            acc[0][1] = fmaf(a.x, b.y, acc[0][1]);
            acc[0][2] = fmaf(a.x, b.z, acc[0][2]);
            acc[0][3] = fmaf(a.x, b.w, acc[0][3]);
            acc[1][0] = fmaf(a.y, b.x, acc[1][0]);
            acc[1][1] = fmaf(a.y, b.y, acc[1][1]);
            acc[1][2] = fmaf(a.y, b.z, acc[1][2]);
            acc[1][3] = fmaf(a.y, b.w, acc[1][3]);
            acc[2][0] = fmaf(a.z, b.x, acc[2][0]);
            acc[2][1] = fmaf(a.z, b.y, acc[2][1]);
            acc[2][2] = fmaf(a.z, b.z, acc[2][2]);
            acc[2][3] = fmaf(a.z, b.w, acc[2][3]);
            acc[3][0] = fmaf(a.w, b.x, acc[3][0]);
            acc[3][1] = fmaf(a.w, b.y, acc[3][1]);
            acc[3][2] = fmaf(a.w, b.z, acc[3][2]);
            acc[3][3] = fmaf(a.w, b.w, acc[3][3]);
        }
        __syncthreads();
    }

    #pragma unroll
    for (int i = 0; i < 4; i++) {
        int m = m0 + (tm << 2) + i;
        int j0 = n0 + (tn << 2);
        float4 o;
        o.x = fmaf(acc[i][0], g_s2[j0 + 0], g_t2[j0 + 0]);
        o.y = fmaf(acc[i][1], g_s2[j0 + 1], g_t2[j0 + 1]);
        o.z = fmaf(acc[i][2], g_s2[j0 + 2], g_t2[j0 + 2]);
        o.w = fmaf(acc[i][3], g_s2[j0 + 3], g_t2[j0 + 3]);
        *(float4*)&out[(size_t)m * 512 + j0] = o;
    }
}

// ---------------------------------------------------------------------------
extern "C" void kernel_launch(void* const* d_in, const int* in_sizes, int n_in,
                              void* d_out, int out_size) {
    const float* x      = (const float*)d_in[0];
    const float* W_qkv  = (const float*)d_in[1];
    const float* b_qkv  = (const float*)d_in[2];
    const float* gamma1 = (const float*)d_in[3];
    const float* beta1  = (const float*)d_in[4];
    const float* mean1  = (const float*)d_in[5];
    const float* var1   = (const float*)d_in[6];
    const float* W_proj = (const float*)d_in[7];
    const float* b_proj = (const float*)d_in[8];
    const float* gamma2 = (const float*)d_in[9];
    const float* beta2  = (const float*)d_in[10];
    const float* mean2  = (const float*)d_in[11];
    const float* var2   = (const float*)d_in[12];
    float* out = (float*)d_out;

    prep_kernel<<<6, 256>>>(b_qkv, gamma1, beta1, mean1, var1,
                            b_proj, gamma2, beta2, mean2, var2);

    dim3 g1(24, 392);
    gemm1_kernel<<<g1, 256>>>(x, W_qkv);

    cudaFuncSetAttribute(attn_kernel, cudaFuncAttributeMaxDynamicSharedMemorySize,
                         ATTN_SMEM_BYTES);
    attn_kernel<<<1024, 256, ATTN_SMEM_BYTES>>>();

    dim3 g2(8, 392);
    gemm2_kernel<<<g2, 256>>>(W_proj, out);
}

// round 6
// speedup vs baseline: 1.1011x; 1.1011x over previous
#include <cuda_runtime.h>
#include <cuda_bf16.h>
#include <cstdint>

// Problem constants
#define SCALE_ATT 0.17677669529663689f   // 32^-0.5

// Scratch (device globals: allocation-free rule)
__device__ float g_q[128*8*196*32];       // [B,H,S,DK]
__device__ float g_k[128*8*196*32];       // [B,H,S,DK]
__device__ float g_v[128*8*196*128];      // [B,H,S,DV]
__device__ float g_hidden[25088*1024];    // scrambled layout, post hard-swish
__device__ float g_s1[1536], g_t1[1536];
__device__ float g_s2[512],  g_t2[512];

// ---------------------------------------------------------------------------
// Helpers (baseline PTX only: ldmatrix sm_75+, mma.sync sm_80+)
// ---------------------------------------------------------------------------
__device__ __forceinline__ uint32_t smem_u32(const void* p) {
    uint32_t a;
    asm("{ .reg .u64 t; cvta.to.shared.u64 t, %1; cvt.u32.u64 %0, t; }" : "=r"(a) : "l"(p));
    return a;
}

#define LDSM_X4(R, addr)                                                      \
    asm volatile("ldmatrix.sync.aligned.m8n8.x4.shared.b16 {%0,%1,%2,%3}, [%4];" \
        : "=r"((R)[0]), "=r"((R)[1]), "=r"((R)[2]), "=r"((R)[3]) : "r"(addr))
#define LDSM_X4T(R, addr)                                                     \
    asm volatile("ldmatrix.sync.aligned.m8n8.x4.trans.shared.b16 {%0,%1,%2,%3}, [%4];" \
        : "=r"((R)[0]), "=r"((R)[1]), "=r"((R)[2]), "=r"((R)[3]) : "r"(addr))

__device__ __forceinline__ void mma_bf16(float* c, const uint32_t* a, const uint32_t* b) {
    asm volatile("mma.sync.aligned.m16n8k16.row.col.f32.bf16.bf16.f32 "
        "{%0,%1,%2,%3}, {%4,%5,%6,%7}, {%8,%9}, {%0,%1,%2,%3};"
        : "+f"(c[0]), "+f"(c[1]), "+f"(c[2]), "+f"(c[3])
        : "r"(a[0]), "r"(a[1]), "r"(a[2]), "r"(a[3]), "r"(b[0]), "r"(b[1]));
}

// split fp32 -> bf16 hi + bf16 lo (residual)
__device__ __forceinline__ void cvt2(float x, float y, uint32_t& h, uint32_t& lo) {
    __nv_bfloat162 hb = __floats2bfloat162_rn(x, y);
    float rx = x - __low2float(hb);
    float ry = y - __high2float(hb);
    __nv_bfloat162 lb = __floats2bfloat162_rn(rx, ry);
    h  = *reinterpret_cast<uint32_t*>(&hb);
    lo = *reinterpret_cast<uint32_t*>(&lb);
}

// ---------------------------------------------------------------------------
// BN fold prep
// ---------------------------------------------------------------------------
__global__ void prep_kernel(const float* __restrict__ b_qkv,
                            const float* __restrict__ gamma1, const float* __restrict__ beta1,
                            const float* __restrict__ mean1,  const float* __restrict__ var1,
                            const float* __restrict__ b_proj,
                            const float* __restrict__ gamma2, const float* __restrict__ beta2,
                            const float* __restrict__ mean2,  const float* __restrict__ var2) {
    int i = blockIdx.x * blockDim.x + threadIdx.x;
    if (i < 1536) {
        float s = gamma1[i] * rsqrtf(var1[i] + 1e-3f);
        g_s1[i] = s;
        g_t1[i] = (b_qkv[i] - mean1[i]) * s + beta1[i];
    }
    if (i < 512) {
        float s = gamma2[i] * rsqrtf(var2[i] + 1e-3f);
        g_s2[i] = s;
        g_t2[i] = (b_proj[i] - mean2[i]) * s + beta2[i];
    }
}

// ---------------------------------------------------------------------------
// HMMA GEMM via mma.sync bf16 3-pass split. CTA tile 128x128, Kc=32, 256 thr.
// SMEM stage (36864 B): Ah[128][40]bf16 @0, Al @10240,
//                       Bh[32][128]bf16 xor-swizzled @20480, Bl @28672.
// Double buffered (73728 B total).
// MODE 0: C = x @ W_qkv  -> BN fold -> scatter q/k/v
// MODE 1: C = g_hidden @ W_proj -> BN fold -> out
// ---------------------------------------------------------------------------
#define STG 36864

template<int KDIM, int NTOT, int MODE>
__global__ __launch_bounds__(256, 1) void hmma_gemm(const float* __restrict__ Aarg,
                                                    const float* __restrict__ Bg,
                                                    float* __restrict__ out) {
    extern __shared__ char smem[];
    uint32_t sb = smem_u32(smem);
    int tid = threadIdx.x, wid = tid >> 5, l = tid & 31;
    int n0 = blockIdx.x * 128, m0 = blockIdx.y * 128;
    int wm = wid & 1, wn = wid >> 1;           // warp tile: m = wm*64, n = wn*32
    const float* Ap = (MODE == 0) ? Aarg : (const float*)g_hidden;

    float acc[4][4][4];
    #pragma unroll
    for (int a = 0; a < 4; a++)
        #pragma unroll
        for (int b = 0; b < 4; b++)
            #pragma unroll
            for (int c = 0; c < 4; c++) acc[a][b][c] = 0.f;

    // staging maps
    int s_arow = tid >> 1, s_ahalf = tid & 1;   // A: 2 threads per 32-float row
    int s_bk = tid >> 3;                        // B: k row
    int s_bn = (tid & 7) * 16;                  // B: 16-float n group

    float4 areg[4], breg[4];

    auto ldg = [&](int kc) {
        const float* ap = Ap + (size_t)(m0 + s_arow) * KDIM + kc * 32 + s_ahalf * 16;
        #pragma unroll
        for (int i = 0; i < 4; i++) areg[i] = *(const float4*)(ap + i * 4);
        const float* bp = Bg + (size_t)(kc * 32 + s_bk) * NTOT + n0 + s_bn;
        #pragma unroll
        for (int i = 0; i < 4; i++) breg[i] = *(const float4*)(bp + i * 4);
    };

    auto cvtst = [&](int buf) {
        char* base = smem + buf * STG;
        uint32_t ha[8], la[8], hb[8], lb[8];
        #pragma unroll
        for (int i = 0; i < 4; i++) {
            cvt2(areg[i].x, areg[i].y, ha[2*i],   la[2*i]);
            cvt2(areg[i].z, areg[i].w, ha[2*i+1], la[2*i+1]);
            cvt2(breg[i].x, breg[i].y, hb[2*i],   lb[2*i]);
            cvt2(breg[i].z, breg[i].w, hb[2*i+1], lb[2*i+1]);
        }
        uint32_t aoff = (uint32_t)(s_arow * 80 + s_ahalf * 32);
        *(uint4*)(base + aoff)              = *(uint4*)&ha[0];
        *(uint4*)(base + aoff + 16)         = *(uint4*)&ha[4];
        *(uint4*)(base + 10240 + aoff)      = *(uint4*)&la[0];
        *(uint4*)(base + 10240 + aoff + 16) = *(uint4*)&la[4];
        int c0 = (tid & 7) * 2;
        #pragma unroll
        for (int ch = 0; ch < 2; ch++) {
            uint32_t cs = (uint32_t)((c0 + ch) ^ (s_bk & 7));
            uint32_t boff = (uint32_t)(s_bk * 256) + cs * 16;
            *(uint4*)(base + 20480 + boff) = *(uint4*)&hb[ch*4];
            *(uint4*)(base + 28672 + boff) = *(uint4*)&lb[ch*4];
        }
    };

    auto compute = [&](int buf) {
        uint32_t base = sb + buf * STG;
        #pragma unroll
        for (int ks = 0; ks < 32; ks += 16) {
            uint32_t ah[4][4], al[4][4], bh[8], bl[8];
            int arow = wm * 64 + (l & 15);
            int acol = ks + ((l >> 4) << 3);
            #pragma unroll
            for (int mt = 0; mt < 4; mt++) {
                uint32_t ad = base + (uint32_t)((arow + mt * 16) * 80 + acol * 2);
                LDSM_X4(ah[mt], ad);
                LDSM_X4(al[mt], ad + 10240);
            }
            int bk = ks + (l & 7) + (((l >> 3) & 1) << 3);
            #pragma unroll
            for (int hf = 0; hf < 2; hf++) {
                int n = wn * 32 + hf * 16 + ((l >> 4) << 3);
                uint32_t cs = (uint32_t)((n >> 3) ^ (bk & 7));
                uint32_t bd = base + 20480 + (uint32_t)(bk * 256) + cs * 16;
                LDSM_X4T(&bh[hf*4], bd);
                LDSM_X4T(&bl[hf*4], bd + 8192);
            }
            #pragma unroll
            for (int mt = 0; mt < 4; mt++)
                #pragma unroll
                for (int nt = 0; nt < 4; nt++)
                    mma_bf16(acc[mt][nt], ah[mt], &bh[nt*2]);
            #pragma unroll
            for (int mt = 0; mt < 4; mt++)
                #pragma unroll
                for (int nt = 0; nt < 4; nt++)
                    mma_bf16(acc[mt][nt], ah[mt], &bl[nt*2]);
            #pragma unroll
            for (int mt = 0; mt < 4; mt++)
                #pragma unroll
                for (int nt = 0; nt < 4; nt++)
                    mma_bf16(acc[mt][nt], al[mt], &bh[nt*2]);
        }
    };

    ldg(0);
    cvtst(0);
    __syncthreads();
    const int NC = KDIM / 32;
    for (int kc = 0; kc < NC; kc++) {
        if (kc + 1 < NC) ldg(kc + 1);
        compute(kc & 1);
        if (kc + 1 < NC) cvtst((kc + 1) & 1);
        __syncthreads();
    }

    // ---- epilogue ----
    #pragma unroll
    for (int mt = 0; mt < 4; mt++) {
        int mrow0 = m0 + wm * 64 + mt * 16 + (l >> 2);
        #pragma unroll
        for (int rr = 0; rr < 2; rr++) {
            int m = mrow0 + rr * 8;
            if (MODE == 0) {
                int bb = m / 196;
                int s  = m - bb * 196;
                #pragma unroll
                for (int nt = 0; nt < 4; nt++) {
                    int j = n0 + wn * 32 + nt * 8 + 2 * (l & 3);
                    #pragma unroll
                    for (int q = 0; q < 2; q++) {
                        int jq = j + q;
                        float v = fmaf(acc[mt][nt][rr*2 + q], g_s1[jq], g_t1[jq]);
                        int h = jq / 192;
                        int r = jq - h * 192;
                        size_t bhs = (size_t)(bb * 8 + h) * 196 + s;
                        if (r < 32)       g_q[bhs * 32 + r] = v;
                        else if (r < 64)  g_k[bhs * 32 + (r - 32)] = v;
                        else              g_v[bhs * 128 + (r - 64)] = v;
                    }
                }
            } else {
                #pragma unroll
                for (int nt = 0; nt < 4; nt++) {
                    int j = n0 + wn * 32 + nt * 8 + 2 * (l & 3);
                    float2 o;
                    o.x = fmaf(acc[mt][nt][rr*2 + 0], g_s2[j],     g_t2[j]);
                    o.y = fmaf(acc[mt][nt][rr*2 + 1], g_s2[j + 1], g_t2[j + 1]);
                    *(float2*)&out[(size_t)m * 512 + j] = o;
                }
            }
        }
    }
}

// ---------------------------------------------------------------------------
// Attention: unchanged from passing R1 kernel (SIMT fp32, one CTA per (b,h))
// ---------------------------------------------------------------------------
#define KSP 33
#define PSP 66
#define QSP 68
#define ATTN_SMEM_FLOATS (196*KSP + 196*128 + 196*PSP + 32*QSP)
#define ATTN_SMEM_BYTES  (ATTN_SMEM_FLOATS * 4)

__global__ __launch_bounds__(256) void attn_kernel() {
    extern __shared__ float sm[];
    float* Ks = sm;
    float* Vs = Ks + 196 * KSP;
    float* Ps = Vs + 196 * 128;
    float* Qs = Ps + 196 * PSP;

    int bh = blockIdx.x;
    int bb = bh >> 3, h = bh & 7;
    const float* qg = g_q + (size_t)bh * 196 * 32;
    const float* kg = g_k + (size_t)bh * 196 * 32;
    const float* vg = g_v + (size_t)bh * 196 * 128;
    int tid = threadIdx.x, w = tid >> 5, l = tid & 31;

    for (int i = tid; i < 196 * 32; i += 256)
        Ks[(i >> 5) * KSP + (i & 31)] = kg[i];
    for (int i = tid; i < 196 * 128; i += 256)
        Vs[i] = vg[i];
    __syncthreads();

    for (int t0 = 0; t0 < 196; t0 += 64) {
        int nr = min(64, 196 - t0);
        for (int i = tid; i < nr * 32; i += 256) {
            int s = i >> 5, d = i & 31;
            Qs[d * QSP + s] = qg[(t0 + s) * 32 + d];
        }
        __syncthreads();

        float acc[56];
        #pragma unroll
        for (int i = 0; i < 56; i++) acc[i] = 0.f;
        int s0 = w << 3;
        #pragma unroll 4
        for (int d = 0; d < 32; d++) {
            float4 qa = *(float4*)(Qs + d * QSP + s0);
            float4 qb = *(float4*)(Qs + d * QSP + s0 + 4);
            #pragma unroll
            for (int t = 0; t < 7; t++) {
                int j = l + (t << 5);
                float kv = Ks[(j < 196 ? j : 195) * KSP + d];
                acc[t * 8 + 0] = fmaf(qa.x, kv, acc[t * 8 + 0]);
                acc[t * 8 + 1] = fmaf(qa.y, kv, acc[t * 8 + 1]);
                acc[t * 8 + 2] = fmaf(qa.z, kv, acc[t * 8 + 2]);
                acc[t * 8 + 3] = fmaf(qa.w, kv, acc[t * 8 + 3]);
                acc[t * 8 + 4] = fmaf(qb.x, kv, acc[t * 8 + 4]);
                acc[t * 8 + 5] = fmaf(qb.y, kv, acc[t * 8 + 5]);
                acc[t * 8 + 6] = fmaf(qb.z, kv, acc[t * 8 + 6]);
                acc[t * 8 + 7] = fmaf(qb.w, kv, acc[t * 8 + 7]);
            }
        }
        #pragma unroll
        for (int t = 0; t < 7; t++) {
            int j = l + (t << 5);
            if (j < 196) {
                #pragma unroll
                for (int i = 0; i < 8; i++)
                    Ps[j * PSP + s0 + i] = acc[t * 8 + i];
            }
        }
        __syncthreads();

        for (int r = w; r < nr; r += 8) {
            float v[7];
            #pragma unroll
            for (int t = 0; t < 7; t++) {
                int j = l + (t << 5);
                v[t] = (j < 196) ? Ps[j * PSP + r] * SCALE_ATT : -1e30f;
            }
            float mx = v[0];
            #pragma unroll
            for (int t = 1; t < 7; t++) mx = fmaxf(mx, v[t]);
            #pragma unroll
            for (int o = 16; o > 0; o >>= 1)
                mx = fmaxf(mx, __shfl_xor_sync(0xffffffffu, mx, o));
            float sum = 0.f;
            #pragma unroll
            for (int t = 0; t < 7; t++) {
                int j = l + (t << 5);
                v[t] = (j < 196) ? __expf(v[t] - mx) : 0.f;
                sum += v[t];
            }
            #pragma unroll
            for (int o = 16; o > 0; o >>= 1)
                sum += __shfl_xor_sync(0xffffffffu, sum, o);
            float inv = 1.0f / sum;
            #pragma unroll
            for (int t = 0; t < 7; t++) {
                int j = l + (t << 5);
                if (j < 196) Ps[j * PSP + r] = v[t] * inv;
            }
        }
        __syncthreads();

        float acc2[32];
        #pragma unroll
        for (int i = 0; i < 32; i++) acc2[i] = 0.f;
        int d0 = w << 4;
        for (int j = 0; j < 196; j++) {
            float p0 = Ps[j * PSP + l];
            float p1 = Ps[j * PSP + l + 32];
            const float* vrow = Vs + j * 128 + d0;
            float4 v0 = *(float4*)(vrow);
            float4 v1 = *(float4*)(vrow + 4);
            float4 v2 = *(float4*)(vrow + 8);
            float4 v3 = *(float4*)(vrow + 12);
            acc2[ 0] = fmaf(p0, v0.x, acc2[ 0]);  acc2[ 1] = fmaf(p0, v0.y, acc2[ 1]);
            acc2[ 2] = fmaf(p0, v0.z, acc2[ 2]);  acc2[ 3] = fmaf(p0, v0.w, acc2[ 3]);
            acc2[ 4] = fmaf(p0, v1.x, acc2[ 4]);  acc2[ 5] = fmaf(p0, v1.y, acc2[ 5]);
            acc2[ 6] = fmaf(p0, v1.z, acc2[ 6]);  acc2[ 7] = fmaf(p0, v1.w, acc2[ 7]);
            acc2[ 8] = fmaf(p0, v2.x, acc2[ 8]);  acc2[ 9] = fmaf(p0, v2.y, acc2[ 9]);
            acc2[10] = fmaf(p0, v2.z, acc2[10]);  acc2[11] = fmaf(p0, v2.w, acc2[11]);
            acc2[12] = fmaf(p0, v3.x, acc2[12]);  acc2[13] = fmaf(p0, v3.y, acc2[13]);
            acc2[14] = fmaf(p0, v3.z, acc2[14]);  acc2[15] = fmaf(p0, v3.w, acc2[15]);
            acc2[16] = fmaf(p1, v0.x, acc2[16]);  acc2[17] = fmaf(p1, v0.y, acc2[17]);
            acc2[18] = fmaf(p1, v0.z, acc2[18]);  acc2[19] = fmaf(p1, v0.w, acc2[19]);
            acc2[20] = fmaf(p1, v1.x, acc2[20]);  acc2[21] = fmaf(p1, v1.y, acc2[21]);
            acc2[22] = fmaf(p1, v1.z, acc2[22]);  acc2[23] = fmaf(p1, v1.w, acc2[23]);
            acc2[24] = fmaf(p1, v2.x, acc2[24]);  acc2[25] = fmaf(p1, v2.y, acc2[25]);
            acc2[26] = fmaf(p1, v2.z, acc2[26]);  acc2[27] = fmaf(p1, v2.w, acc2[27]);
            acc2[28] = fmaf(p1, v3.x, acc2[28]);  acc2[29] = fmaf(p1, v3.y, acc2[29]);
            acc2[30] = fmaf(p1, v3.z, acc2[30]);  acc2[31] = fmaf(p1, v3.w, acc2[31]);
        }

        size_t base = (size_t)bb * 200704 + (size_t)h * 25088 + t0;
        #pragma unroll
        for (int g = 0; g < 2; g++) {
            int sl = l + (g << 5);
            if (sl < nr) {
                #pragma unroll
                for (int t = 0; t < 16; t++) {
                    float xv = acc2[g * 16 + t];
                    float hs = xv * __saturatef((xv + 3.0f) * (1.0f / 6.0f));
                    g_hidden[base + (size_t)(d0 + t) * 196 + sl] = hs;
                }
            }
        }
        __syncthreads();
    }
}

// ---------------------------------------------------------------------------
extern "C" void kernel_launch(void* const* d_in, const int* in_sizes, int n_in,
                              void* d_out, int out_size) {
    const float* x      = (const float*)d_in[0];
    const float* W_qkv  = (const float*)d_in[1];
    const float* b_qkv  = (const float*)d_in[2];
    const float* gamma1 = (const float*)d_in[3];
    const float* beta1  = (const float*)d_in[4];
    const float* mean1  = (const float*)d_in[5];
    const float* var1   = (const float*)d_in[6];
    const float* W_proj = (const float*)d_in[7];
    const float* b_proj = (const float*)d_in[8];
    const float* gamma2 = (const float*)d_in[9];
    const float* beta2  = (const float*)d_in[10];
    const float* mean2  = (const float*)d_in[11];
    const float* var2   = (const float*)d_in[12];
    float* out = (float*)d_out;

    prep_kernel<<<6, 256>>>(b_qkv, gamma1, beta1, mean1, var1,
                            b_proj, gamma2, beta2, mean2, var2);

    cudaFuncSetAttribute(hmma_gemm<512, 1536, 0>,
                         cudaFuncAttributeMaxDynamicSharedMemorySize, 2 * STG);
    cudaFuncSetAttribute(hmma_gemm<1024, 512, 1>,
                         cudaFuncAttributeMaxDynamicSharedMemorySize, 2 * STG);
    cudaFuncSetAttribute(attn_kernel, cudaFuncAttributeMaxDynamicSharedMemorySize,
                         ATTN_SMEM_BYTES);

    // GEMM1: [25088,512] @ [512,1536] -> q/k/v
    dim3 g1(12, 196);
    hmma_gemm<512, 1536, 0><<<g1, 256, 2 * STG>>>(x, W_qkv, nullptr);

    // Attention
    attn_kernel<<<1024, 256, ATTN_SMEM_BYTES>>>();

    // GEMM2: [25088,1024] @ [1024,512] -> out
    dim3 g2(4, 196);
    hmma_gemm<1024, 512, 1><<<g2, 256, 2 * STG>>>(nullptr, W_proj, out);
}

// round 7
// speedup vs baseline: 1.2425x; 1.1285x over previous
#include <cuda_runtime.h>
#include <cuda_bf16.h>
#include <cstdint>

#define SCALE_ATT 0.17677669529663689f   // 32^-0.5

// Scratch (device globals: allocation-free rule)
__device__ float g_q[128*8*196*32];       // [B,H,S,DK]
__device__ float g_k[128*8*196*32];       // [B,H,S,DK]
__device__ float g_v[128*8*196*128];      // [B,H,S,DV]
__device__ float g_s1[1536], g_t1[1536];
__device__ float g_s2[512],  g_t2[512];

// Pre-converted bf16 hi/lo operands
__device__ __align__(16) __nv_bfloat16 g_xh[25088*512],  g_xl[25088*512];
__device__ __align__(16) __nv_bfloat16 g_w1h[512*1536],  g_w1l[512*1536];
__device__ __align__(16) __nv_bfloat16 g_w2h[1024*512],  g_w2l[1024*512];
__device__ __align__(16) __nv_bfloat16 g_hh[25088*1024], g_hl[25088*1024];

// ---------------------------------------------------------------------------
// Helpers (baseline PTX only: ldmatrix sm_75+, mma.sync sm_80+, cp.async sm_80+)
// ---------------------------------------------------------------------------
__device__ __forceinline__ uint32_t smem_u32(const void* p) {
    uint32_t a;
    asm("{ .reg .u64 t; cvta.to.shared.u64 t, %1; cvt.u32.u64 %0, t; }" : "=r"(a) : "l"(p));
    return a;
}
#define LDSM_X4(R, addr)                                                      \
    asm volatile("ldmatrix.sync.aligned.m8n8.x4.shared.b16 {%0,%1,%2,%3}, [%4];" \
        : "=r"((R)[0]), "=r"((R)[1]), "=r"((R)[2]), "=r"((R)[3]) : "r"(addr))
#define LDSM_X4T(R, addr)                                                     \
    asm volatile("ldmatrix.sync.aligned.m8n8.x4.trans.shared.b16 {%0,%1,%2,%3}, [%4];" \
        : "=r"((R)[0]), "=r"((R)[1]), "=r"((R)[2]), "=r"((R)[3]) : "r"(addr))

__device__ __forceinline__ void mma_bf16(float* c, const uint32_t* a, const uint32_t* b) {
    asm volatile("mma.sync.aligned.m16n8k16.row.col.f32.bf16.bf16.f32 "
        "{%0,%1,%2,%3}, {%4,%5,%6,%7}, {%8,%9}, {%0,%1,%2,%3};"
        : "+f"(c[0]), "+f"(c[1]), "+f"(c[2]), "+f"(c[3])
        : "r"(a[0]), "r"(a[1]), "r"(a[2]), "r"(a[3]), "r"(b[0]), "r"(b[1]));
}
__device__ __forceinline__ void cp16(uint32_t dst, const void* src) {
    asm volatile("cp.async.cg.shared.global [%0], [%1], 16;" :: "r"(dst), "l"(src));
}
#define CP_COMMIT() asm volatile("cp.async.commit_group;" ::: "memory")
#define CP_WAIT1()  asm volatile("cp.async.wait_group 1;" ::: "memory")
#define CP_WAIT0()  asm volatile("cp.async.wait_group 0;" ::: "memory")

// ---------------------------------------------------------------------------
// BN fold prep
// ---------------------------------------------------------------------------
__global__ void prep_kernel(const float* __restrict__ b_qkv,
                            const float* __restrict__ gamma1, const float* __restrict__ beta1,
                            const float* __restrict__ mean1,  const float* __restrict__ var1,
                            const float* __restrict__ b_proj,
                            const float* __restrict__ gamma2, const float* __restrict__ beta2,
                            const float* __restrict__ mean2,  const float* __restrict__ var2) {
    int i = blockIdx.x * blockDim.x + threadIdx.x;
    if (i < 1536) {
        float s = gamma1[i] * rsqrtf(var1[i] + 1e-3f);
        g_s1[i] = s;
        g_t1[i] = (b_qkv[i] - mean1[i]) * s + beta1[i];
    }
    if (i < 512) {
        float s = gamma2[i] * rsqrtf(var2[i] + 1e-3f);
        g_s2[i] = s;
        g_t2[i] = (b_proj[i] - mean2[i]) * s + beta2[i];
    }
}

// fp32 -> bf16 hi/lo pre-conversion
__global__ void cvt_kernel(const float* __restrict__ src, __nv_bfloat16* __restrict__ dh,
                           __nv_bfloat16* __restrict__ dl, int n4) {
    int i = blockIdx.x * blockDim.x + threadIdx.x;
    if (i < n4) {
        float4 v = ((const float4*)src)[i];
        __nv_bfloat162 h0 = __floats2bfloat162_rn(v.x, v.y);
        __nv_bfloat162 h1 = __floats2bfloat162_rn(v.z, v.w);
        __nv_bfloat162 l0 = __floats2bfloat162_rn(v.x - __low2float(h0), v.y - __high2float(h0));
        __nv_bfloat162 l1 = __floats2bfloat162_rn(v.z - __low2float(h1), v.w - __high2float(h1));
        ((__nv_bfloat162*)dh)[i*2]   = h0;
        ((__nv_bfloat162*)dh)[i*2+1] = h1;
        ((__nv_bfloat162*)dl)[i*2]   = l0;
        ((__nv_bfloat162*)dl)[i*2+1] = l1;
    }
}

// ---------------------------------------------------------------------------
// HMMA GEMM: pre-converted bf16 hi/lo + cp.async 3-stage pipeline.
// CTA 128x128, Kc=32, 256 threads, warp tile 64x32 (2x4 warp grid).
// Stage (32768 B): Ah[128][32] @0 (64B rows, chunk swizzle c^((r>>1)&3)),
//                  Al @8192, Bh[32][128] @16384 (256B rows, nch^(k&7)), Bl @24576.
// 3-pass split: AhBh + AhBl + AlBh, fp32 accum.
// MODE 0: x @ W_qkv -> BN fold -> scatter q/k/v.  MODE 1: hidden @ W_proj -> out
// ---------------------------------------------------------------------------
#define STG 32768

template<int KDIM, int NTOT, int MODE>
__global__ __launch_bounds__(256, 2) void hmma_gemm(float* __restrict__ out) {
    extern __shared__ char smem[];
    uint32_t sb = smem_u32(smem);
    int tid = threadIdx.x, wid = tid >> 5, l = tid & 31;
    int n0 = blockIdx.x * 128, m0 = blockIdx.y * 128;
    int wm = wid & 1, wn = wid >> 1;

    const __nv_bfloat16* Ahg = (MODE == 0) ? g_xh  : g_hh;
    const __nv_bfloat16* Alg = (MODE == 0) ? g_xl  : g_hl;
    const __nv_bfloat16* Bhg = (MODE == 0) ? g_w1h : g_w2h;
    const __nv_bfloat16* Blg = (MODE == 0) ? g_w1l : g_w2l;

    float acc[4][4][4];
    #pragma unroll
    for (int a = 0; a < 4; a++)
        #pragma unroll
        for (int b = 0; b < 4; b++)
            #pragma unroll
            for (int c = 0; c < 4; c++) acc[a][b][c] = 0.f;

    // cp.async maps
    int a_r = tid >> 1;                      // A row, 2 chunks per thread
    int a_c0 = (tid & 1) * 2;
    int b_q0 = tid * 2;                      // B chunk ids

    auto issue = [&](int kc) {
        uint32_t stg = sb + (kc % 3) * STG;
        const __nv_bfloat16* ah = Ahg + (size_t)(m0 + a_r) * KDIM + kc * 32;
        const __nv_bfloat16* al = Alg + (size_t)(m0 + a_r) * KDIM + kc * 32;
        #pragma unroll
        for (int i = 0; i < 2; i++) {
            int c = a_c0 + i;
            uint32_t dst = stg + a_r * 64 + ((uint32_t)(c ^ ((a_r >> 1) & 3)) << 4);
            cp16(dst, ah + c * 8);
            cp16(dst + 8192, al + c * 8);
        }
        #pragma unroll
        for (int i = 0; i < 2; i++) {
            int q = b_q0 + i;
            int k = q >> 4, nch = q & 15;
            uint32_t dst = stg + 16384 + k * 256 + ((uint32_t)(nch ^ (k & 7)) << 4);
            const __nv_bfloat16* bsrc = Bhg + (size_t)(kc * 32 + k) * NTOT + n0 + nch * 8;
            const __nv_bfloat16* bsrl = Blg + (size_t)(kc * 32 + k) * NTOT + n0 + nch * 8;
            cp16(dst, bsrc);
            cp16(dst + 8192, bsrl);
        }
    };

    auto compute = [&](int s) {
        uint32_t base = sb + s * STG;
        #pragma unroll
        for (int ks = 0; ks < 32; ks += 16) {
            uint32_t ah[16], al[16], bh[8], bl[8];
            int c = (ks >> 3) + (l >> 4);
            uint32_t aaddr[4];
            #pragma unroll
            for (int mt = 0; mt < 4; mt++) {
                int r = wm * 64 + mt * 16 + (l & 15);
                aaddr[mt] = base + r * 64 + ((uint32_t)(c ^ ((r >> 1) & 3)) << 4);
                LDSM_X4(&ah[mt*4], aaddr[mt]);
            }
            int bk = ks + (l & 7) + (((l >> 3) & 1) << 3);
            #pragma unroll
            for (int hf = 0; hf < 2; hf++) {
                int nch = (wn * 32 + hf * 16 + ((l >> 4) << 3)) >> 3;
                uint32_t bd = base + 16384 + bk * 256 + ((uint32_t)(nch ^ (bk & 7)) << 4);
                LDSM_X4T(&bh[hf*4], bd);
                LDSM_X4T(&bl[hf*4], bd + 8192);
            }
            #pragma unroll
            for (int mt = 0; mt < 4; mt++)
                #pragma unroll
                for (int nt = 0; nt < 4; nt++)
                    mma_bf16(acc[mt][nt], &ah[mt*4], &bh[nt*2]);
            #pragma unroll
            for (int mt = 0; mt < 4; mt++)
                #pragma unroll
                for (int nt = 0; nt < 4; nt++)
                    mma_bf16(acc[mt][nt], &ah[mt*4], &bl[nt*2]);
            #pragma unroll
            for (int mt = 0; mt < 4; mt++)
                LDSM_X4(&al[mt*4], aaddr[mt] + 8192);
            #pragma unroll
            for (int mt = 0; mt < 4; mt++)
                #pragma unroll
                for (int nt = 0; nt < 4; nt++)
                    mma_bf16(acc[mt][nt], &al[mt*4], &bh[nt*2]);
        }
    };

    const int NC = KDIM / 32;
    issue(0);
    CP_COMMIT();
    issue(1);
    CP_COMMIT();
    for (int kc = 0; kc < NC; kc++) {
        if (kc < NC - 1) CP_WAIT1(); else CP_WAIT0();
        __syncthreads();
        if (kc + 2 < NC) issue(kc + 2);
        CP_COMMIT();
        compute(kc % 3);
    }

    // ---- epilogue (identical to verified R4 map) ----
    #pragma unroll
    for (int mt = 0; mt < 4; mt++) {
        int mrow0 = m0 + wm * 64 + mt * 16 + (l >> 2);
        #pragma unroll
        for (int rr = 0; rr < 2; rr++) {
            int m = mrow0 + rr * 8;
            if (MODE == 0) {
                int bb = m / 196;
                int s  = m - bb * 196;
                #pragma unroll
                for (int nt = 0; nt < 4; nt++) {
                    int j = n0 + wn * 32 + nt * 8 + 2 * (l & 3);
                    #pragma unroll
                    for (int q = 0; q < 2; q++) {
                        int jq = j + q;
                        float v = fmaf(acc[mt][nt][rr*2 + q], g_s1[jq], g_t1[jq]);
                        int h = jq / 192;
                        int r = jq - h * 192;
                        size_t bhs = (size_t)(bb * 8 + h) * 196 + s;
                        if (r < 32)       g_q[bhs * 32 + r] = v;
                        else if (r < 64)  g_k[bhs * 32 + (r - 32)] = v;
                        else              g_v[bhs * 128 + (r - 64)] = v;
                    }
                }
            } else {
                #pragma unroll
                for (int nt = 0; nt < 4; nt++) {
                    int j = n0 + wn * 32 + nt * 8 + 2 * (l & 3);
                    float2 o;
                    o.x = fmaf(acc[mt][nt][rr*2 + 0], g_s2[j],     g_t2[j]);
                    o.y = fmaf(acc[mt][nt][rr*2 + 1], g_s2[j + 1], g_t2[j + 1]);
                    *(float2*)&out[(size_t)m * 512 + j] = o;
                }
            }
        }
    }
}

// ---------------------------------------------------------------------------
// Attention (unchanged compute; epilogue now emits bf16 hi/lo hidden)
// ---------------------------------------------------------------------------
#define KSP 33
#define PSP 66
#define QSP 68
#define ATTN_SMEM_FLOATS (196*KSP + 196*128 + 196*PSP + 32*QSP)
#define ATTN_SMEM_BYTES  (ATTN_SMEM_FLOATS * 4)

__global__ __launch_bounds__(256) void attn_kernel() {
    extern __shared__ float sm[];
    float* Ks = sm;
    float* Vs = Ks + 196 * KSP;
    float* Ps = Vs + 196 * 128;
    float* Qs = Ps + 196 * PSP;

    int bh = blockIdx.x;
    int bb = bh >> 3, h = bh & 7;
    const float* qg = g_q + (size_t)bh * 196 * 32;
    const float* kg = g_k + (size_t)bh * 196 * 32;
    const float* vg = g_v + (size_t)bh * 196 * 128;
    int tid = threadIdx.x, w = tid >> 5, l = tid & 31;

    for (int i = tid; i < 196 * 32; i += 256)
        Ks[(i >> 5) * KSP + (i & 31)] = kg[i];
    for (int i = tid; i < 196 * 128; i += 256)
        Vs[i] = vg[i];
    __syncthreads();

    for (int t0 = 0; t0 < 196; t0 += 64) {
        int nr = min(64, 196 - t0);
        for (int i = tid; i < nr * 32; i += 256) {
            int s = i >> 5, d = i & 31;
            Qs[d * QSP + s] = qg[(t0 + s) * 32 + d];
        }
        __syncthreads();

        float acc[56];
        #pragma unroll
        for (int i = 0; i < 56; i++) acc[i] = 0.f;
        int s0 = w << 3;
        #pragma unroll 4
        for (int d = 0; d < 32; d++) {
            float4 qa = *(float4*)(Qs + d * QSP + s0);
            float4 qb = *(float4*)(Qs + d * QSP + s0 + 4);
            #pragma unroll
            for (int t = 0; t < 7; t++) {
                int j = l + (t << 5);
                float kv = Ks[(j < 196 ? j : 195) * KSP + d];
                acc[t * 8 + 0] = fmaf(qa.x, kv, acc[t * 8 + 0]);
                acc[t * 8 + 1] = fmaf(qa.y, kv, acc[t * 8 + 1]);
                acc[t * 8 + 2] = fmaf(qa.z, kv, acc[t * 8 + 2]);
                acc[t * 8 + 3] = fmaf(qa.w, kv, acc[t * 8 + 3]);
                acc[t * 8 + 4] = fmaf(qb.x, kv, acc[t * 8 + 4]);
                acc[t * 8 + 5] = fmaf(qb.y, kv, acc[t * 8 + 5]);
                acc[t * 8 + 6] = fmaf(qb.z, kv, acc[t * 8 + 6]);
                acc[t * 8 + 7] = fmaf(qb.w, kv, acc[t * 8 + 7]);
            }
        }
        #pragma unroll
        for (int t = 0; t < 7; t++) {
            int j = l + (t << 5);
            if (j < 196) {
                #pragma unroll
                for (int i = 0; i < 8; i++)
                    Ps[j * PSP + s0 + i] = acc[t * 8 + i];
            }
        }
        __syncthreads();

        for (int r = w; r < nr; r += 8) {
            float v[7];
            #pragma unroll
            for (int t = 0; t < 7; t++) {
                int j = l + (t << 5);
                v[t] = (j < 196) ? Ps[j * PSP + r] * SCALE_ATT : -1e30f;
            }
            float mx = v[0];
            #pragma unroll
            for (int t = 1; t < 7; t++) mx = fmaxf(mx, v[t]);
            #pragma unroll
            for (int o = 16; o > 0; o >>= 1)
                mx = fmaxf(mx, __shfl_xor_sync(0xffffffffu, mx, o));
            float sum = 0.f;
            #pragma unroll
            for (int t = 0; t < 7; t++) {
                int j = l + (t << 5);
                v[t] = (j < 196) ? __expf(v[t] - mx) : 0.f;
                sum += v[t];
            }
            #pragma unroll
            for (int o = 16; o > 0; o >>= 1)
                sum += __shfl_xor_sync(0xffffffffu, sum, o);
            float inv = 1.0f / sum;
            #pragma unroll
            for (int t = 0; t < 7; t++) {
                int j = l + (t << 5);
                if (j < 196) Ps[j * PSP + r] = v[t] * inv;
            }
        }
        __syncthreads();

        float acc2[32];
        #pragma unroll
        for (int i = 0; i < 32; i++) acc2[i] = 0.f;
        int d0 = w << 4;
        for (int j = 0; j < 196; j++) {
            float p0 = Ps[j * PSP + l];
            float p1 = Ps[j * PSP + l + 32];
            const float* vrow = Vs + j * 128 + d0;
            float4 v0 = *(float4*)(vrow);
            float4 v1 = *(float4*)(vrow + 4);
            float4 v2 = *(float4*)(vrow + 8);
            float4 v3 = *(float4*)(vrow + 12);
            acc2[ 0] = fmaf(p0, v0.x, acc2[ 0]);  acc2[ 1] = fmaf(p0, v0.y, acc2[ 1]);
            acc2[ 2] = fmaf(p0, v0.z, acc2[ 2]);  acc2[ 3] = fmaf(p0, v0.w, acc2[ 3]);
            acc2[ 4] = fmaf(p0, v1.x, acc2[ 4]);  acc2[ 5] = fmaf(p0, v1.y, acc2[ 5]);
            acc2[ 6] = fmaf(p0, v1.z, acc2[ 6]);  acc2[ 7] = fmaf(p0, v1.w, acc2[ 7]);
            acc2[ 8] = fmaf(p0, v2.x, acc2[ 8]);  acc2[ 9] = fmaf(p0, v2.y, acc2[ 9]);
            acc2[10] = fmaf(p0, v2.z, acc2[10]);  acc2[11] = fmaf(p0, v2.w, acc2[11]);
            acc2[12] = fmaf(p0, v3.x, acc2[12]);  acc2[13] = fmaf(p0, v3.y, acc2[13]);
            acc2[14] = fmaf(p0, v3.z, acc2[14]);  acc2[15] = fmaf(p0, v3.w, acc2[15]);
            acc2[16] = fmaf(p1, v0.x, acc2[16]);  acc2[17] = fmaf(p1, v0.y, acc2[17]);
            acc2[18] = fmaf(p1, v0.z, acc2[18]);  acc2[19] = fmaf(p1, v0.w, acc2[19]);
            acc2[20] = fmaf(p1, v1.x, acc2[20]);  acc2[21] = fmaf(p1, v1.y, acc2[21]);
            acc2[22] = fmaf(p1, v1.z, acc2[22]);  acc2[23] = fmaf(p1, v1.w, acc2[23]);
            acc2[24] = fmaf(p1, v2.x, acc2[24]);  acc2[25] = fmaf(p1, v2.y, acc2[25]);
            acc2[26] = fmaf(p1, v2.z, acc2[26]);  acc2[27] = fmaf(p1, v2.w, acc2[27]);
            acc2[28] = fmaf(p1, v3.x, acc2[28]);  acc2[29] = fmaf(p1, v3.y, acc2[29]);
            acc2[30] = fmaf(p1, v3.z, acc2[30]);  acc2[31] = fmaf(p1, v3.w, acc2[31]);
        }

        size_t base = (size_t)bb * 200704 + (size_t)h * 25088 + t0;
        #pragma unroll
        for (int g = 0; g < 2; g++) {
            int sl = l + (g << 5);
            if (sl < nr) {
                #pragma unroll
                for (int t = 0; t < 16; t++) {
                    float xv = acc2[g * 16 + t];
                    float hs = xv * __saturatef((xv + 3.0f) * (1.0f / 6.0f));
                    size_t idx = base + (size_t)(d0 + t) * 196 + sl;
                    __nv_bfloat16 hh = __float2bfloat16(hs);
                    g_hh[idx] = hh;
                    g_hl[idx] = __float2bfloat16(hs - __bfloat162float(hh));
                }
            }
        }
        __syncthreads();
    }
}

// ---------------------------------------------------------------------------
extern "C" void kernel_launch(void* const* d_in, const int* in_sizes, int n_in,
                              void* d_out, int out_size) {
    const float* x      = (const float*)d_in[0];
    const float* W_qkv  = (const float*)d_in[1];
    const float* b_qkv  = (const float*)d_in[2];
    const float* gamma1 = (const float*)d_in[3];
    const float* beta1  = (const float*)d_in[4];
    const float* mean1  = (const float*)d_in[5];
    const float* var1   = (const float*)d_in[6];
    const float* W_proj = (const float*)d_in[7];
    const float* b_proj = (const float*)d_in[8];
    const float* gamma2 = (const float*)d_in[9];
    const float* beta2  = (const float*)d_in[10];
    const float* mean2  = (const float*)d_in[11];
    const float* var2   = (const float*)d_in[12];
    float* out = (float*)d_out;

    prep_kernel<<<6, 256>>>(b_qkv, gamma1, beta1, mean1, var1,
                            b_proj, gamma2, beta2, mean2, var2);

    // Pre-convert x, W_qkv, W_proj to bf16 hi/lo
    {
        __nv_bfloat16 *xh, *xl, *w1h, *w1l, *w2h, *w2l;
        cudaGetSymbolAddress((void**)&xh,  g_xh);
        cudaGetSymbolAddress((void**)&xl,  g_xl);
        cudaGetSymbolAddress((void**)&w1h, g_w1h);
        cudaGetSymbolAddress((void**)&w1l, g_w1l);
        cudaGetSymbolAddress((void**)&w2h, g_w2h);
        cudaGetSymbolAddress((void**)&w2l, g_w2l);
        cvt_kernel<<<(25088*512/4 + 255)/256, 256>>>(x, xh, xl, 25088*512/4);
        cvt_kernel<<<(512*1536/4 + 255)/256, 256>>>(W_qkv, w1h, w1l, 512*1536/4);
        cvt_kernel<<<(1024*512/4 + 255)/256, 256>>>(W_proj, w2h, w2l, 1024*512/4);
    }

    cudaFuncSetAttribute(hmma_gemm<512, 1536, 0>,
                         cudaFuncAttributeMaxDynamicSharedMemorySize, 3 * STG);
    cudaFuncSetAttribute(hmma_gemm<1024, 512, 1>,
                         cudaFuncAttributeMaxDynamicSharedMemorySize, 3 * STG);
    cudaFuncSetAttribute(attn_kernel, cudaFuncAttributeMaxDynamicSharedMemorySize,
                         ATTN_SMEM_BYTES);

    // GEMM1: [25088,512] @ [512,1536] -> q/k/v
    dim3 g1(12, 196);
    hmma_gemm<512, 1536, 0><<<g1, 256, 3 * STG>>>(nullptr);

    // Attention
    attn_kernel<<<1024, 256, ATTN_SMEM_BYTES>>>();

    // GEMM2: [25088,1024] @ [1024,512] -> out
    dim3 g2(4, 196);
    hmma_gemm<1024, 512, 1><<<g2, 256, 3 * STG>>>(out);
}

// round 9
// speedup vs baseline: 2.4059x; 1.9362x over previous
#include <cuda_runtime.h>
#include <cuda_bf16.h>
#include <cstdint>

#define SCALE_ATT 0.17677669529663689f   // 32^-0.5

// Scratch (device globals: allocation-free rule)
__device__ float g_q[128*8*196*32];       // [B,H,S,DK]
__device__ float g_k[128*8*196*32];       // [B,H,S,DK]
__device__ float g_v[128*8*196*128];      // [B,H,S,DV]
__device__ float g_s1[1536], g_t1[1536];
__device__ float g_s2[512],  g_t2[512];

// Pre-converted bf16 hi/lo operands
__device__ __align__(16) __nv_bfloat16 g_xh[25088*512],  g_xl[25088*512];
__device__ __align__(16) __nv_bfloat16 g_w1h[512*1536],  g_w1l[512*1536];
__device__ __align__(16) __nv_bfloat16 g_w2h[1024*512],  g_w2l[1024*512];
__device__ __align__(16) __nv_bfloat16 g_hh[25088*1024], g_hl[25088*1024];

// ---------------------------------------------------------------------------
// Helpers (baseline PTX only: ldmatrix sm_75+, mma.sync sm_80+, cp.async sm_80+)
// ---------------------------------------------------------------------------
__device__ __forceinline__ uint32_t smem_u32(const void* p) {
    uint32_t a;
    asm("{ .reg .u64 t; cvta.to.shared.u64 t, %1; cvt.u32.u64 %0, t; }" : "=r"(a) : "l"(p));
    return a;
}
#define LDSM_X4(R, addr)                                                      \
    asm volatile("ldmatrix.sync.aligned.m8n8.x4.shared.b16 {%0,%1,%2,%3}, [%4];" \
        : "=r"((R)[0]), "=r"((R)[1]), "=r"((R)[2]), "=r"((R)[3]) : "r"(addr))
#define LDSM_X4T(R, addr)                                                     \
    asm volatile("ldmatrix.sync.aligned.m8n8.x4.trans.shared.b16 {%0,%1,%2,%3}, [%4];" \
        : "=r"((R)[0]), "=r"((R)[1]), "=r"((R)[2]), "=r"((R)[3]) : "r"(addr))

__device__ __forceinline__ void mma_bf16(float* c, const uint32_t* a, const uint32_t* b) {
    asm volatile("mma.sync.aligned.m16n8k16.row.col.f32.bf16.bf16.f32 "
        "{%0,%1,%2,%3}, {%4,%5,%6,%7}, {%8,%9}, {%0,%1,%2,%3};"
        : "+f"(c[0]), "+f"(c[1]), "+f"(c[2]), "+f"(c[3])
        : "r"(a[0]), "r"(a[1]), "r"(a[2]), "r"(a[3]), "r"(b[0]), "r"(b[1]));
}
__device__ __forceinline__ void cp16(uint32_t dst, const void* src) {
    asm volatile("cp.async.cg.shared.global [%0], [%1], 16;" :: "r"(dst), "l"(src));
}
#define CP_COMMIT() asm volatile("cp.async.commit_group;" ::: "memory")
#define CP_WAIT1()  asm volatile("cp.async.wait_group 1;" ::: "memory")
#define CP_WAIT0()  asm volatile("cp.async.wait_group 0;" ::: "memory")

// fast exp2 via MUFU
__device__ __forceinline__ float fexp2(float x) {
    float r;
    asm("ex2.approx.f32 %0, %1;" : "=f"(r) : "f"(x));
    return r;
}

// ---------------------------------------------------------------------------
// BN fold prep
// ---------------------------------------------------------------------------
__global__ void prep_kernel(const float* __restrict__ b_qkv,
                            const float* __restrict__ gamma1, const float* __restrict__ beta1,
                            const float* __restrict__ mean1,  const float* __restrict__ var1,
                            const float* __restrict__ b_proj,
                            const float* __restrict__ gamma2, const float* __restrict__ beta2,
                            const float* __restrict__ mean2,  const float* __restrict__ var2) {
    int i = blockIdx.x * blockDim.x + threadIdx.x;
    if (i < 1536) {
        float s = gamma1[i] * rsqrtf(var1[i] + 1e-3f);
        g_s1[i] = s;
        g_t1[i] = (b_qkv[i] - mean1[i]) * s + beta1[i];
    }
    if (i < 512) {
        float s = gamma2[i] * rsqrtf(var2[i] + 1e-3f);
        g_s2[i] = s;
        g_t2[i] = (b_proj[i] - mean2[i]) * s + beta2[i];
    }
}

// fp32 -> bf16 hi/lo pre-conversion
__global__ void cvt_kernel(const float* __restrict__ src, __nv_bfloat16* __restrict__ dh,
                           __nv_bfloat16* __restrict__ dl, int n4) {
    int i = blockIdx.x * blockDim.x + threadIdx.x;
    if (i < n4) {
        float4 v = ((const float4*)src)[i];
        __nv_bfloat162 h0 = __floats2bfloat162_rn(v.x, v.y);
        __nv_bfloat162 h1 = __floats2bfloat162_rn(v.z, v.w);
        __nv_bfloat162 l0 = __floats2bfloat162_rn(v.x - __low2float(h0), v.y - __high2float(h0));
        __nv_bfloat162 l1 = __floats2bfloat162_rn(v.z - __low2float(h1), v.w - __high2float(h1));
        ((__nv_bfloat162*)dh)[i*2]   = h0;
        ((__nv_bfloat162*)dh)[i*2+1] = h1;
        ((__nv_bfloat162*)dl)[i*2]   = l0;
        ((__nv_bfloat162*)dl)[i*2+1] = l1;
    }
}

// ---------------------------------------------------------------------------
// HMMA GEMM (unchanged from R7 passing version)
// ---------------------------------------------------------------------------
#define STG 32768

template<int KDIM, int NTOT, int MODE>
__global__ __launch_bounds__(256, 2) void hmma_gemm(float* __restrict__ out) {
    extern __shared__ char smem[];
    uint32_t sb = smem_u32(smem);
    int tid = threadIdx.x, wid = tid >> 5, l = tid & 31;
    int n0 = blockIdx.x * 128, m0 = blockIdx.y * 128;
    int wm = wid & 1, wn = wid >> 1;

    const __nv_bfloat16* Ahg = (MODE == 0) ? g_xh  : g_hh;
    const __nv_bfloat16* Alg = (MODE == 0) ? g_xl  : g_hl;
    const __nv_bfloat16* Bhg = (MODE == 0) ? g_w1h : g_w2h;
    const __nv_bfloat16* Blg = (MODE == 0) ? g_w1l : g_w2l;

    float acc[4][4][4];
    #pragma unroll
    for (int a = 0; a < 4; a++)
        #pragma unroll
        for (int b = 0; b < 4; b++)
            #pragma unroll
            for (int c = 0; c < 4; c++) acc[a][b][c] = 0.f;

    int a_r = tid >> 1;
    int a_c0 = (tid & 1) * 2;
    int b_q0 = tid * 2;

    auto issue = [&](int kc) {
        uint32_t stg = sb + (kc % 3) * STG;
        const __nv_bfloat16* ah = Ahg + (size_t)(m0 + a_r) * KDIM + kc * 32;
        const __nv_bfloat16* al = Alg + (size_t)(m0 + a_r) * KDIM + kc * 32;
        #pragma unroll
        for (int i = 0; i < 2; i++) {
            int c = a_c0 + i;
            uint32_t dst = stg + a_r * 64 + ((uint32_t)(c ^ ((a_r >> 1) & 3)) << 4);
            cp16(dst, ah + c * 8);
            cp16(dst + 8192, al + c * 8);
        }
        #pragma unroll
        for (int i = 0; i < 2; i++) {
            int q = b_q0 + i;
            int k = q >> 4, nch = q & 15;
            uint32_t dst = stg + 16384 + k * 256 + ((uint32_t)(nch ^ (k & 7)) << 4);
            const __nv_bfloat16* bsrc = Bhg + (size_t)(kc * 32 + k) * NTOT + n0 + nch * 8;
            const __nv_bfloat16* bsrl = Blg + (size_t)(kc * 32 + k) * NTOT + n0 + nch * 8;
            cp16(dst, bsrc);
            cp16(dst + 8192, bsrl);
        }
    };

    auto compute = [&](int s) {
        uint32_t base = sb + s * STG;
        #pragma unroll
        for (int ks = 0; ks < 32; ks += 16) {
            uint32_t ah[16], al[16], bh[8], bl[8];
            int c = (ks >> 3) + (l >> 4);
            uint32_t aaddr[4];
            #pragma unroll
            for (int mt = 0; mt < 4; mt++) {
                int r = wm * 64 + mt * 16 + (l & 15);
                aaddr[mt] = base + r * 64 + ((uint32_t)(c ^ ((r >> 1) & 3)) << 4);
                LDSM_X4(&ah[mt*4], aaddr[mt]);
            }
            int bk = ks + (l & 7) + (((l >> 3) & 1) << 3);
            #pragma unroll
            for (int hf = 0; hf < 2; hf++) {
                int nch = (wn * 32 + hf * 16 + ((l >> 4) << 3)) >> 3;
                uint32_t bd = base + 16384 + bk * 256 + ((uint32_t)(nch ^ (bk & 7)) << 4);
                LDSM_X4T(&bh[hf*4], bd);
                LDSM_X4T(&bl[hf*4], bd + 8192);
            }
            #pragma unroll
            for (int mt = 0; mt < 4; mt++)
                #pragma unroll
                for (int nt = 0; nt < 4; nt++)
                    mma_bf16(acc[mt][nt], &ah[mt*4], &bh[nt*2]);
            #pragma unroll
            for (int mt = 0; mt < 4; mt++)
                #pragma unroll
                for (int nt = 0; nt < 4; nt++)
                    mma_bf16(acc[mt][nt], &ah[mt*4], &bl[nt*2]);
            #pragma unroll
            for (int mt = 0; mt < 4; mt++)
                LDSM_X4(&al[mt*4], aaddr[mt] + 8192);
            #pragma unroll
            for (int mt = 0; mt < 4; mt++)
                #pragma unroll
                for (int nt = 0; nt < 4; nt++)
                    mma_bf16(acc[mt][nt], &al[mt*4], &bh[nt*2]);
        }
    };

    const int NC = KDIM / 32;
    issue(0);
    CP_COMMIT();
    issue(1);
    CP_COMMIT();
    for (int kc = 0; kc < NC; kc++) {
        if (kc < NC - 1) CP_WAIT1(); else CP_WAIT0();
        __syncthreads();
        if (kc + 2 < NC) issue(kc + 2);
        CP_COMMIT();
        compute(kc % 3);
    }

    #pragma unroll
    for (int mt = 0; mt < 4; mt++) {
        int mrow0 = m0 + wm * 64 + mt * 16 + (l >> 2);
        #pragma unroll
        for (int rr = 0; rr < 2; rr++) {
            int m = mrow0 + rr * 8;
            if (MODE == 0) {
                int bb = m / 196;
                int s  = m - bb * 196;
                #pragma unroll
                for (int nt = 0; nt < 4; nt++) {
                    int j = n0 + wn * 32 + nt * 8 + 2 * (l & 3);
                    #pragma unroll
                    for (int q = 0; q < 2; q++) {
                        int jq = j + q;
                        float v = fmaf(acc[mt][nt][rr*2 + q], g_s1[jq], g_t1[jq]);
                        int h = jq / 192;
                        int r = jq - h * 192;
                        size_t bhs = (size_t)(bb * 8 + h) * 196 + s;
                        if (r < 32)       g_q[bhs * 32 + r] = v;
                        else if (r < 64)  g_k[bhs * 32 + (r - 32)] = v;
                        else              g_v[bhs * 128 + (r - 64)] = v;
                    }
                }
            } else {
                #pragma unroll
                for (int nt = 0; nt < 4; nt++) {
                    int j = n0 + wn * 32 + nt * 8 + 2 * (l & 3);
                    float2 o;
                    o.x = fmaf(acc[mt][nt][rr*2 + 0], g_s2[j],     g_t2[j]);
                    o.y = fmaf(acc[mt][nt][rr*2 + 1], g_s2[j + 1], g_t2[j + 1]);
                    *(float2*)&out[(size_t)m * 512 + j] = o;
                }
            }
        }
    }
}

// ---------------------------------------------------------------------------
// HMMA attention: one CTA per (b,h). 256 threads, 8 warps.
// SMEM: QH@0, QL@13312, KH@26624, KL@39936 (208x64B swizzled rows),
//       VH@53248, VL@106496 (208x256B swizzled rows),
//       per-warp epilogue staging @159744 (8 x 5120B, 20-float rows).
// Warp w handles query m16-tiles {w, w+8 (if <13)}.
// QK^T: 3-pass split bf16; softmax in C-frags; P repacked in-place as A-frags;
// AV: 3-pass; hard_swish; transposed store to g_hh/g_hl ([b,h,d,s] natural).
// ---------------------------------------------------------------------------
#define AQH 0
#define AQL 13312
#define AKH 26624
#define AKL 39936
#define AVH 53248
#define AVL 106496
#define ASTG 159744
#define ATTN_SMEM 200704

__global__ __launch_bounds__(256, 1) void attn_kernel() {
    extern __shared__ char smem[];
    uint32_t sb = smem_u32(smem);
    int tid = threadIdx.x, w = tid >> 5, l = tid & 31;
    int bh = blockIdx.x;
    int bb = bh >> 3, hh = bh & 7;
    const float* qg = g_q + (size_t)bh * 196 * 32;
    const float* kg = g_k + (size_t)bh * 196 * 32;
    const float* vg = g_v + (size_t)bh * 196 * 128;

    // ---- stage Q,K (hi/lo bf16, 64B rows, chunk swizzle c^((r>>1)&3)) ----
    for (int r = tid >> 1; r < 208; r += 128) {
        int half = tid & 1;
        float4 v[4];
        if (r < 196) {
            #pragma unroll
            for (int i = 0; i < 4; i++) v[i] = *(const float4*)(qg + r*32 + half*16 + i*4);
        } else {
            #pragma unroll
            for (int i = 0; i < 4; i++) v[i] = make_float4(0.f, 0.f, 0.f, 0.f);
        }
        uint32_t hv[8], lv[8];
        #pragma unroll
        for (int i = 0; i < 4; i++) {
            __nv_bfloat162 h0 = __floats2bfloat162_rn(v[i].x, v[i].y);
            __nv_bfloat162 h1 = __floats2bfloat162_rn(v[i].z, v[i].w);
            __nv_bfloat162 l0 = __floats2bfloat162_rn(v[i].x - __low2float(h0), v[i].y - __high2float(h0));
            __nv_bfloat162 l1 = __floats2bfloat162_rn(v[i].z - __low2float(h1), v[i].w - __high2float(h1));
            hv[i*2] = *(uint32_t*)&h0;  hv[i*2+1] = *(uint32_t*)&h1;
            lv[i*2] = *(uint32_t*)&l0;  lv[i*2+1] = *(uint32_t*)&l1;
        }
        #pragma unroll
        for (int cc = 0; cc < 2; cc++) {
            int c = half*2 + cc;
            uint32_t off = r*64 + ((uint32_t)(c ^ ((r>>1)&3)) << 4);
            *(uint4*)(smem + AQH + off) = *(uint4*)&hv[cc*4];
            *(uint4*)(smem + AQL + off) = *(uint4*)&lv[cc*4];
        }
        // K
        if (r < 196) {
            #pragma unroll
            for (int i = 0; i < 4; i++) v[i] = *(const float4*)(kg + r*32 + half*16 + i*4);
        } else {
            #pragma unroll
            for (int i = 0; i < 4; i++) v[i] = make_float4(0.f, 0.f, 0.f, 0.f);
        }
        #pragma unroll
        for (int i = 0; i < 4; i++) {
            __nv_bfloat162 h0 = __floats2bfloat162_rn(v[i].x, v[i].y);
            __nv_bfloat162 h1 = __floats2bfloat162_rn(v[i].z, v[i].w);
            __nv_bfloat162 l0 = __floats2bfloat162_rn(v[i].x - __low2float(h0), v[i].y - __high2float(h0));
            __nv_bfloat162 l1 = __floats2bfloat162_rn(v[i].z - __low2float(h1), v[i].w - __high2float(h1));
            hv[i*2] = *(uint32_t*)&h0;  hv[i*2+1] = *(uint32_t*)&h1;
            lv[i*2] = *(uint32_t*)&l0;  lv[i*2+1] = *(uint32_t*)&l1;
        }
        #pragma unroll
        for (int cc = 0; cc < 2; cc++) {
            int c = half*2 + cc;
            uint32_t off = r*64 + ((uint32_t)(c ^ ((r>>1)&3)) << 4);
            *(uint4*)(smem + AKH + off) = *(uint4*)&hv[cc*4];
            *(uint4*)(smem + AKL + off) = *(uint4*)&lv[cc*4];
        }
    }
    // ---- stage V (hi/lo, 256B rows, chunk swizzle c^(r&7)) ----
    for (int r = tid >> 3; r < 208; r += 32) {
        int ch = tid & 7;
        float4 v[4];
        if (r < 196) {
            #pragma unroll
            for (int i = 0; i < 4; i++) v[i] = *(const float4*)(vg + r*128 + ch*16 + i*4);
        } else {
            #pragma unroll
            for (int i = 0; i < 4; i++) v[i] = make_float4(0.f, 0.f, 0.f, 0.f);
        }
        uint32_t hv[8], lv[8];
        #pragma unroll
        for (int i = 0; i < 4; i++) {
            __nv_bfloat162 h0 = __floats2bfloat162_rn(v[i].x, v[i].y);
            __nv_bfloat162 h1 = __floats2bfloat162_rn(v[i].z, v[i].w);
            __nv_bfloat162 l0 = __floats2bfloat162_rn(v[i].x - __low2float(h0), v[i].y - __high2float(h0));
            __nv_bfloat162 l1 = __floats2bfloat162_rn(v[i].z - __low2float(h1), v[i].w - __high2float(h1));
            hv[i*2] = *(uint32_t*)&h0;  hv[i*2+1] = *(uint32_t*)&h1;
            lv[i*2] = *(uint32_t*)&l0;  lv[i*2+1] = *(uint32_t*)&l1;
        }
        #pragma unroll
        for (int cc = 0; cc < 2; cc++) {
            int c = ch*2 + cc;
            uint32_t off = r*256 + ((uint32_t)(c ^ (r&7)) << 4);
            *(uint4*)(smem + AVH + off) = *(uint4*)&hv[cc*4];
            *(uint4*)(smem + AVL + off) = *(uint4*)&lv[cc*4];
        }
    }
    __syncthreads();

    float* stg = (float*)(smem + ASTG + w * 5120);
    const float CEXP = SCALE_ATT * 1.44269504f;

    for (int mi = 0; mi < 2; mi++) {
        int mt = w + mi * 8;
        if (mt > 12) continue;

        // ---- scores: sc[26 ntiles][4], 3-pass split bf16 ----
        float sc[26][4];
        #pragma unroll
        for (int t = 0; t < 26; t++)
            #pragma unroll
            for (int j = 0; j < 4; j++) sc[t][j] = 0.f;

        #pragma unroll
        for (int ks = 0; ks < 2; ks++) {
            uint32_t qh[4], ql[4];
            int qr = mt*16 + (l & 15);
            int qc = ks*2 + (l >> 4);
            uint32_t qa = sb + AQH + qr*64 + ((uint32_t)(qc ^ ((qr>>1)&3)) << 4);
            LDSM_X4(qh, qa);
            LDSM_X4(ql, qa + (AQL - AQH));
            #pragma unroll
            for (int ng = 0; ng < 13; ng++) {
                uint32_t kh[4], kl[4];
                int kr = ng*16 + (l & 15);
                uint32_t ka = sb + AKH + kr*64 + ((uint32_t)(qc ^ ((kr>>1)&3)) << 4);
                LDSM_X4(kh, ka);
                LDSM_X4(kl, ka + (AKL - AKH));
                uint32_t b0[2] = {kh[0], kh[2]}, b1[2] = {kh[1], kh[3]};
                uint32_t c0[2] = {kl[0], kl[2]}, c1[2] = {kl[1], kl[3]};
                mma_bf16(sc[2*ng],   qh, b0);
                mma_bf16(sc[2*ng+1], qh, b1);
                mma_bf16(sc[2*ng],   qh, c0);
                mma_bf16(sc[2*ng+1], qh, c1);
                mma_bf16(sc[2*ng],   ql, b0);
                mma_bf16(sc[2*ng+1], ql, b1);
            }
        }

        // ---- mask key cols >= 196 ----
        if ((l & 3) >= 2) {
            sc[24][0] = sc[24][1] = sc[24][2] = sc[24][3] = -1e30f;
        }
        sc[25][0] = sc[25][1] = sc[25][2] = sc[25][3] = -1e30f;

        // ---- softmax (rows rA = l/4 in c0/c1, rB = rA+8 in c2/c3) ----
        float mxA = -1e30f, mxB = -1e30f;
        #pragma unroll
        for (int t = 0; t < 26; t++) {
            mxA = fmaxf(mxA, fmaxf(sc[t][0], sc[t][1]));
            mxB = fmaxf(mxB, fmaxf(sc[t][2], sc[t][3]));
        }
        #pragma unroll
        for (int o = 1; o <= 2; o <<= 1) {
            mxA = fmaxf(mxA, __shfl_xor_sync(0xffffffffu, mxA, o));
            mxB = fmaxf(mxB, __shfl_xor_sync(0xffffffffu, mxB, o));
        }
        float smA = 0.f, smB = 0.f;
        #pragma unroll
        for (int t = 0; t < 26; t++) {
            sc[t][0] = fexp2(CEXP * (sc[t][0] - mxA));
            sc[t][1] = fexp2(CEXP * (sc[t][1] - mxA));
            sc[t][2] = fexp2(CEXP * (sc[t][2] - mxB));
            sc[t][3] = fexp2(CEXP * (sc[t][3] - mxB));
            smA += sc[t][0] + sc[t][1];
            smB += sc[t][2] + sc[t][3];
        }
        #pragma unroll
        for (int o = 1; o <= 2; o <<= 1) {
            smA += __shfl_xor_sync(0xffffffffu, smA, o);
            smB += __shfl_xor_sync(0xffffffffu, smB, o);
        }
        float ivA = 1.0f / smA, ivB = 1.0f / smB;

        // ---- repack P in place: sc[t] = {hiA, hiB, loA, loB} packed bf16x2 ----
        #pragma unroll
        for (int t = 0; t < 26; t++) {
            float p0 = sc[t][0] * ivA, p1 = sc[t][1] * ivA;
            float p2 = sc[t][2] * ivB, p3 = sc[t][3] * ivB;
            __nv_bfloat162 hA = __floats2bfloat162_rn(p0, p1);
            __nv_bfloat162 hB = __floats2bfloat162_rn(p2, p3);
            __nv_bfloat162 lA = __floats2bfloat162_rn(p0 - __low2float(hA), p1 - __high2float(hA));
            __nv_bfloat162 lB = __floats2bfloat162_rn(p2 - __low2float(hB), p3 - __high2float(hB));
            sc[t][0] = *(float*)&hA;
            sc[t][1] = *(float*)&hB;
            sc[t][2] = *(float*)&lA;
            sc[t][3] = *(float*)&lB;
        }

        // ---- AV: 3-pass over 13 k-steps, 16 d-ntiles ----
        float av[16][4];
        #pragma unroll
        for (int t = 0; t < 16; t++)
            #pragma unroll
            for (int j = 0; j < 4; j++) av[t][j] = 0.f;

        #pragma unroll 1
        for (int kt = 0; kt < 13; kt++) {
            uint32_t aPh[4] = { *(uint32_t*)&sc[2*kt][0], *(uint32_t*)&sc[2*kt][1],
                                *(uint32_t*)&sc[2*kt+1][0], *(uint32_t*)&sc[2*kt+1][1] };
            uint32_t aPl[4] = { *(uint32_t*)&sc[2*kt][2], *(uint32_t*)&sc[2*kt][3],
                                *(uint32_t*)&sc[2*kt+1][2], *(uint32_t*)&sc[2*kt+1][3] };
            int bk = kt*16 + (l & 7) + (((l >> 3) & 1) << 3);
            #pragma unroll
            for (int dg = 0; dg < 8; dg++) {
                uint32_t vh[4], vl[4];
                int nch = dg*2 + (l >> 4);
                uint32_t bd = sb + AVH + bk*256 + ((uint32_t)(nch ^ (bk & 7)) << 4);
                LDSM_X4T(vh, bd);
                LDSM_X4T(vl, bd + (AVL - AVH));
                mma_bf16(av[2*dg],   aPh, &vh[0]);
                mma_bf16(av[2*dg+1], aPh, &vh[2]);
                mma_bf16(av[2*dg],   aPh, &vl[0]);
                mma_bf16(av[2*dg+1], aPh, &vl[2]);
                mma_bf16(av[2*dg],   aPl, &vh[0]);
                mma_bf16(av[2*dg+1], aPl, &vh[2]);
            }
        }

        // ---- hard_swish + transposed store via per-warp staging ----
        int s0 = mt * 16;
        int nv = 196 - s0;
        if (nv > 16) nv = 16;
        int rA = l >> 2;
        size_t gbase = (size_t)bb * 200704 + (size_t)hh * 25088;

        #pragma unroll 1
        for (int h2 = 0; h2 < 2; h2++) {
            __syncwarp();
            #pragma unroll
            for (int nt = 8*h2; nt < 8*h2 + 8; nt++) {
                int dl0 = 2*(l & 3) + 8*(nt - 8*h2);
                float x0 = av[nt][0], x1 = av[nt][1], x2 = av[nt][2], x3 = av[nt][3];
                x0 = x0 * __saturatef((x0 + 3.f) * (1.f/6.f));
                x1 = x1 * __saturatef((x1 + 3.f) * (1.f/6.f));
                x2 = x2 * __saturatef((x2 + 3.f) * (1.f/6.f));
                x3 = x3 * __saturatef((x3 + 3.f) * (1.f/6.f));
                stg[dl0*20 + rA]       = x0;
                stg[(dl0+1)*20 + rA]   = x1;
                stg[dl0*20 + rA + 8]   = x2;
                stg[(dl0+1)*20 + rA + 8] = x3;
            }
            __syncwarp();
            #pragma unroll
            for (int rr = 0; rr < 2; rr++) {
                int row = rr*32 + l;
                int d = h2*64 + row;
                float4 f0 = *(float4*)(stg + row*20);
                float4 f1 = *(float4*)(stg + row*20 + 4);
                float4 f2 = *(float4*)(stg + row*20 + 8);
                float4 f3 = *(float4*)(stg + row*20 + 12);
                uint32_t ph[8], pl[8];
                float fv[16] = {f0.x,f0.y,f0.z,f0.w, f1.x,f1.y,f1.z,f1.w,
                                f2.x,f2.y,f2.z,f2.w, f3.x,f3.y,f3.z,f3.w};
                #pragma unroll
                for (int i = 0; i < 8; i++) {
                    __nv_bfloat162 hbv = __floats2bfloat162_rn(fv[2*i], fv[2*i+1]);
                    __nv_bfloat162 lbv = __floats2bfloat162_rn(fv[2*i] - __low2float(hbv),
                                                               fv[2*i+1] - __high2float(hbv));
                    ph[i] = *(uint32_t*)&hbv;
                    pl[i] = *(uint32_t*)&lbv;
                }
                size_t gidx = gbase + (size_t)d * 196 + s0;
                if (nv == 16) {
                    #pragma unroll
                    for (int i = 0; i < 4; i++) {
                        *(uint2*)(g_hh + gidx + i*4) = make_uint2(ph[2*i], ph[2*i+1]);
                        *(uint2*)(g_hl + gidx + i*4) = make_uint2(pl[2*i], pl[2*i+1]);
                    }
                } else {
                    *(uint2*)(g_hh + gidx) = make_uint2(ph[0], ph[1]);
                    *(uint2*)(g_hl + gidx) = make_uint2(pl[0], pl[1]);
                }
            }
        }
    }
}

// ---------------------------------------------------------------------------
extern "C" void kernel_launch(void* const* d_in, const int* in_sizes, int n_in,
                              void* d_out, int out_size) {
    const float* x      = (const float*)d_in[0];
    const float* W_qkv  = (const float*)d_in[1];
    const float* b_qkv  = (const float*)d_in[2];
    const float* gamma1 = (const float*)d_in[3];
    const float* beta1  = (const float*)d_in[4];
    const float* mean1  = (const float*)d_in[5];
    const float* var1   = (const float*)d_in[6];
    const float* W_proj = (const float*)d_in[7];
    const float* b_proj = (const float*)d_in[8];
    const float* gamma2 = (const float*)d_in[9];
    const float* beta2  = (const float*)d_in[10];
    const float* mean2  = (const float*)d_in[11];
    const float* var2   = (const float*)d_in[12];
    float* out = (float*)d_out;

    prep_kernel<<<6, 256>>>(b_qkv, gamma1, beta1, mean1, var1,
                            b_proj, gamma2, beta2, mean2, var2);

    {
        __nv_bfloat16 *xh, *xl, *w1h, *w1l, *w2h, *w2l;
        cudaGetSymbolAddress((void**)&xh,  g_xh);
        cudaGetSymbolAddress((void**)&xl,  g_xl);
        cudaGetSymbolAddress((void**)&w1h, g_w1h);
        cudaGetSymbolAddress((void**)&w1l, g_w1l);
        cudaGetSymbolAddress((void**)&w2h, g_w2h);
        cudaGetSymbolAddress((void**)&w2l, g_w2l);
        cvt_kernel<<<(25088*512/4 + 255)/256, 256>>>(x, xh, xl, 25088*512/4);
        cvt_kernel<<<(512*1536/4 + 255)/256, 256>>>(W_qkv, w1h, w1l, 512*1536/4);
        cvt_kernel<<<(1024*512/4 + 255)/256, 256>>>(W_proj, w2h, w2l, 1024*512/4);
    }

    cudaFuncSetAttribute(hmma_gemm<512, 1536, 0>,
                         cudaFuncAttributeMaxDynamicSharedMemorySize, 3 * STG);
    cudaFuncSetAttribute(hmma_gemm<1024, 512, 1>,
                         cudaFuncAttributeMaxDynamicSharedMemorySize, 3 * STG);
    cudaFuncSetAttribute(attn_kernel,
                         cudaFuncAttributeMaxDynamicSharedMemorySize, ATTN_SMEM);

    // GEMM1: [25088,512] @ [512,1536] -> q/k/v
    dim3 g1(12, 196);
    hmma_gemm<512, 1536, 0><<<g1, 256, 3 * STG>>>(nullptr);

    // Attention (HMMA)
    attn_kernel<<<1024, 256, ATTN_SMEM>>>();

    // GEMM2: [25088,1024] @ [1024,512] -> out
    dim3 g2(4, 196);
    hmma_gemm<1024, 512, 1><<<g2, 256, 3 * STG>>>(out);
}